// round 2
// baseline (speedup 1.0000x reference)
#include <cuda_runtime.h>

// Problem constants
#define NT 8192
#define CT 512
#define HT 8

// Scratch (allocation-free rule: __device__ globals)
__device__ float g_Q[NT * CT];
__device__ float g_K[NT * CT];
__device__ float g_Y[NT * CT];
__device__ float g_S[(size_t)NT * NT];   // 268 MB

// Tiling
#define BM 128
#define BN 128
#define BK 16
#define TM 8
#define TN 8
// 256 threads: 16x16, each 8x8 micro-tile

// ---------------------------------------------------------------------------
// C[M x Nc] = A[M x Kc] @ B[Kc x Nc] (+ bias broadcast over rows, optional)
// ---------------------------------------------------------------------------
__global__ __launch_bounds__(256)
void gemm_nn_kernel(const float* __restrict__ A, const float* __restrict__ B,
                    const float* __restrict__ bias, float* __restrict__ C,
                    int M, int Nc, int Kc)
{
    __shared__ float As[BK][BM + 4];
    __shared__ float Bs[BK][BN];

    const int tid = threadIdx.x;
    const int tx = tid & 15;
    const int ty = tid >> 4;
    const int row0 = blockIdx.y * BM;
    const int col0 = blockIdx.x * BN;

    float acc[TM][TN] = {};

    for (int kt = 0; kt < Kc; kt += BK) {
        #pragma unroll
        for (int it = 0; it < 2; ++it) {
            int idx = tid + it * 256;
            // A tile: 128 rows x 16 k, transposed into As[k][m]
            int r = idx >> 2, q = idx & 3;
            float4 a = *reinterpret_cast<const float4*>(
                &A[(size_t)(row0 + r) * Kc + kt + q * 4]);
            As[q * 4 + 0][r] = a.x;
            As[q * 4 + 1][r] = a.y;
            As[q * 4 + 2][r] = a.z;
            As[q * 4 + 3][r] = a.w;
            // B tile: 16 k-rows x 128 cols, direct
            int br = idx >> 5, bq = idx & 31;
            *reinterpret_cast<float4*>(&Bs[br][bq * 4]) =
                *reinterpret_cast<const float4*>(
                    &B[(size_t)(kt + br) * Nc + col0 + bq * 4]);
        }
        __syncthreads();

        #pragma unroll
        for (int kk = 0; kk < BK; ++kk) {
            float ar[TM], brg[TN];
            float4 a0 = *reinterpret_cast<const float4*>(&As[kk][ty * TM]);
            float4 a1 = *reinterpret_cast<const float4*>(&As[kk][ty * TM + 4]);
            ar[0] = a0.x; ar[1] = a0.y; ar[2] = a0.z; ar[3] = a0.w;
            ar[4] = a1.x; ar[5] = a1.y; ar[6] = a1.z; ar[7] = a1.w;
            float4 b0 = *reinterpret_cast<const float4*>(&Bs[kk][tx * TN]);
            float4 b1 = *reinterpret_cast<const float4*>(&Bs[kk][tx * TN + 4]);
            brg[0] = b0.x; brg[1] = b0.y; brg[2] = b0.z; brg[3] = b0.w;
            brg[4] = b1.x; brg[5] = b1.y; brg[6] = b1.z; brg[7] = b1.w;
            #pragma unroll
            for (int i = 0; i < TM; ++i)
                #pragma unroll
                for (int j = 0; j < TN; ++j)
                    acc[i][j] = fmaf(ar[i], brg[j], acc[i][j]);
        }
        __syncthreads();
    }

    float bv[TN];
    #pragma unroll
    for (int j = 0; j < TN; ++j)
        bv[j] = bias ? bias[col0 + tx * TN + j] : 0.0f;

    #pragma unroll
    for (int i = 0; i < TM; ++i) {
        size_t base = (size_t)(row0 + ty * TM + i) * Nc + col0 + tx * TN;
        float4 o0, o1;
        o0.x = acc[i][0] + bv[0]; o0.y = acc[i][1] + bv[1];
        o0.z = acc[i][2] + bv[2]; o0.w = acc[i][3] + bv[3];
        o1.x = acc[i][4] + bv[4]; o1.y = acc[i][5] + bv[5];
        o1.z = acc[i][6] + bv[6]; o1.w = acc[i][7] + bv[7];
        *reinterpret_cast<float4*>(&C[base])     = o0;
        *reinterpret_cast<float4*>(&C[base + 4]) = o1;
    }
}

// ---------------------------------------------------------------------------
// C[M x Nc] = A[M x Kc] @ B[Nc x Kc]^T   (both operands K-contiguous, "NT")
// ---------------------------------------------------------------------------
__global__ __launch_bounds__(256)
void gemm_nt_kernel(const float* __restrict__ A, const float* __restrict__ B,
                    float* __restrict__ C, int M, int Nc, int Kc)
{
    __shared__ float As[BK][BM + 4];
    __shared__ float Bs[BK][BN + 4];

    const int tid = threadIdx.x;
    const int tx = tid & 15;
    const int ty = tid >> 4;
    const int row0 = blockIdx.y * BM;
    const int col0 = blockIdx.x * BN;

    float acc[TM][TN] = {};

    for (int kt = 0; kt < Kc; kt += BK) {
        #pragma unroll
        for (int it = 0; it < 2; ++it) {
            int idx = tid + it * 256;
            int r = idx >> 2, q = idx & 3;
            float4 a = *reinterpret_cast<const float4*>(
                &A[(size_t)(row0 + r) * Kc + kt + q * 4]);
            As[q * 4 + 0][r] = a.x;
            As[q * 4 + 1][r] = a.y;
            As[q * 4 + 2][r] = a.z;
            As[q * 4 + 3][r] = a.w;
            float4 b = *reinterpret_cast<const float4*>(
                &B[(size_t)(col0 + r) * Kc + kt + q * 4]);
            Bs[q * 4 + 0][r] = b.x;
            Bs[q * 4 + 1][r] = b.y;
            Bs[q * 4 + 2][r] = b.z;
            Bs[q * 4 + 3][r] = b.w;
        }
        __syncthreads();

        #pragma unroll
        for (int kk = 0; kk < BK; ++kk) {
            float ar[TM], brg[TN];
            float4 a0 = *reinterpret_cast<const float4*>(&As[kk][ty * TM]);
            float4 a1 = *reinterpret_cast<const float4*>(&As[kk][ty * TM + 4]);
            ar[0] = a0.x; ar[1] = a0.y; ar[2] = a0.z; ar[3] = a0.w;
            ar[4] = a1.x; ar[5] = a1.y; ar[6] = a1.z; ar[7] = a1.w;
            float4 b0 = *reinterpret_cast<const float4*>(&Bs[kk][tx * TN]);
            float4 b1 = *reinterpret_cast<const float4*>(&Bs[kk][tx * TN + 4]);
            brg[0] = b0.x; brg[1] = b0.y; brg[2] = b0.z; brg[3] = b0.w;
            brg[4] = b1.x; brg[5] = b1.y; brg[6] = b1.z; brg[7] = b1.w;
            #pragma unroll
            for (int i = 0; i < TM; ++i)
                #pragma unroll
                for (int j = 0; j < TN; ++j)
                    acc[i][j] = fmaf(ar[i], brg[j], acc[i][j]);
        }
        __syncthreads();
    }

    #pragma unroll
    for (int i = 0; i < TM; ++i) {
        size_t base = (size_t)(row0 + ty * TM + i) * Nc + col0 + tx * TN;
        float4 o0, o1;
        o0.x = acc[i][0]; o0.y = acc[i][1]; o0.z = acc[i][2]; o0.w = acc[i][3];
        o1.x = acc[i][4]; o1.y = acc[i][5]; o1.z = acc[i][6]; o1.w = acc[i][7];
        *reinterpret_cast<float4*>(&C[base])     = o0;
        *reinterpret_cast<float4*>(&C[base + 4]) = o1;
    }
}

// ---------------------------------------------------------------------------
// In-place row softmax over NT columns; one block per row, row cached in smem.
// ---------------------------------------------------------------------------
__global__ __launch_bounds__(256)
void softmax_kernel(float* __restrict__ S)
{
    __shared__ float row[NT];
    __shared__ float red[256];

    const int tid = threadIdx.x;
    float* p = S + (size_t)blockIdx.x * NT;
    float4* p4 = reinterpret_cast<float4*>(p);
    float4* r4 = reinterpret_cast<float4*>(row);

    // load + local max
    float mx = -3.0e38f;
    for (int i = tid; i < NT / 4; i += 256) {
        float4 v = p4[i];
        r4[i] = v;
        mx = fmaxf(mx, fmaxf(fmaxf(v.x, v.y), fmaxf(v.z, v.w)));
    }
    red[tid] = mx;
    __syncthreads();
    for (int s = 128; s > 0; s >>= 1) {
        if (tid < s) red[tid] = fmaxf(red[tid], red[tid + s]);
        __syncthreads();
    }
    mx = red[0];
    __syncthreads();

    // exp + local sum
    float sum = 0.0f;
    for (int i = tid; i < NT / 4; i += 256) {
        float4 v = r4[i];
        v.x = expf(v.x - mx); v.y = expf(v.y - mx);
        v.z = expf(v.z - mx); v.w = expf(v.w - mx);
        sum += (v.x + v.y) + (v.z + v.w);
        r4[i] = v;
    }
    red[tid] = sum;
    __syncthreads();
    for (int s = 128; s > 0; s >>= 1) {
        if (tid < s) red[tid] += red[tid + s];
        __syncthreads();
    }
    float inv = 1.0f / red[0];
    __syncthreads();

    for (int i = tid; i < NT / 4; i += 256) {
        float4 v = r4[i];
        v.x *= inv; v.y *= inv; v.z *= inv; v.w *= inv;
        p4[i] = v;
    }
}

// ---------------------------------------------------------------------------
// out[n,c] = (1/H) * sum_h relu( (Y @ Wk[h])[n,c] + bk[h,c] )
// M=NT, N=CT, K=CT, head loop outermost per tile.
// ---------------------------------------------------------------------------
__global__ __launch_bounds__(256)
void heads_kernel(const float* __restrict__ Y, const float* __restrict__ Wk,
                  const float* __restrict__ bk, float* __restrict__ out)
{
    __shared__ float As[BK][BM + 4];
    __shared__ float Bs[BK][BN];

    const int tid = threadIdx.x;
    const int tx = tid & 15;
    const int ty = tid >> 4;
    const int row0 = blockIdx.y * BM;
    const int col0 = blockIdx.x * BN;

    float oacc[TM][TN] = {};

    for (int h = 0; h < HT; ++h) {
        const float* B = Wk + (size_t)h * CT * CT;
        float acc[TM][TN] = {};

        for (int kt = 0; kt < CT; kt += BK) {
            #pragma unroll
            for (int it = 0; it < 2; ++it) {
                int idx = tid + it * 256;
                int r = idx >> 2, q = idx & 3;
                float4 a = *reinterpret_cast<const float4*>(
                    &Y[(size_t)(row0 + r) * CT + kt + q * 4]);
                As[q * 4 + 0][r] = a.x;
                As[q * 4 + 1][r] = a.y;
                As[q * 4 + 2][r] = a.z;
                As[q * 4 + 3][r] = a.w;
                int br = idx >> 5, bq = idx & 31;
                *reinterpret_cast<float4*>(&Bs[br][bq * 4]) =
                    *reinterpret_cast<const float4*>(
                        &B[(size_t)(kt + br) * CT + col0 + bq * 4]);
            }
            __syncthreads();

            #pragma unroll
            for (int kk = 0; kk < BK; ++kk) {
                float ar[TM], brg[TN];
                float4 a0 = *reinterpret_cast<const float4*>(&As[kk][ty * TM]);
                float4 a1 = *reinterpret_cast<const float4*>(&As[kk][ty * TM + 4]);
                ar[0] = a0.x; ar[1] = a0.y; ar[2] = a0.z; ar[3] = a0.w;
                ar[4] = a1.x; ar[5] = a1.y; ar[6] = a1.z; ar[7] = a1.w;
                float4 b0 = *reinterpret_cast<const float4*>(&Bs[kk][tx * TN]);
                float4 b1 = *reinterpret_cast<const float4*>(&Bs[kk][tx * TN + 4]);
                brg[0] = b0.x; brg[1] = b0.y; brg[2] = b0.z; brg[3] = b0.w;
                brg[4] = b1.x; brg[5] = b1.y; brg[6] = b1.z; brg[7] = b1.w;
                #pragma unroll
                for (int i = 0; i < TM; ++i)
                    #pragma unroll
                    for (int j = 0; j < TN; ++j)
                        acc[i][j] = fmaf(ar[i], brg[j], acc[i][j]);
            }
            __syncthreads();
        }

        float bv[TN];
        #pragma unroll
        for (int j = 0; j < TN; ++j)
            bv[j] = bk[(size_t)h * CT + col0 + tx * TN + j];
        #pragma unroll
        for (int i = 0; i < TM; ++i)
            #pragma unroll
            for (int j = 0; j < TN; ++j)
                oacc[i][j] += fmaxf(acc[i][j] + bv[j], 0.0f);
    }

    const float scale = 1.0f / (float)HT;
    #pragma unroll
    for (int i = 0; i < TM; ++i) {
        size_t base = (size_t)(row0 + ty * TM + i) * CT + col0 + tx * TN;
        float4 o0, o1;
        o0.x = oacc[i][0] * scale; o0.y = oacc[i][1] * scale;
        o0.z = oacc[i][2] * scale; o0.w = oacc[i][3] * scale;
        o1.x = oacc[i][4] * scale; o1.y = oacc[i][5] * scale;
        o1.z = oacc[i][6] * scale; o1.w = oacc[i][7] * scale;
        *reinterpret_cast<float4*>(&out[base])     = o0;
        *reinterpret_cast<float4*>(&out[base + 4]) = o1;
    }
}

// ---------------------------------------------------------------------------
extern "C" void kernel_launch(void* const* d_in, const int* in_sizes, int n_in,
                              void* d_out, int out_size)
{
    const float* x       = (const float*)d_in[0];
    const float* W_theta = (const float*)d_in[1];
    const float* b_theta = (const float*)d_in[2];
    const float* W_phi   = (const float*)d_in[3];
    const float* b_phi   = (const float*)d_in[4];
    const float* W_k     = (const float*)d_in[5];
    const float* b_k     = (const float*)d_in[6];
    float* out = (float*)d_out;

    float *Q, *K, *S, *Y;
    cudaGetSymbolAddress((void**)&Q, g_Q);
    cudaGetSymbolAddress((void**)&K, g_K);
    cudaGetSymbolAddress((void**)&S, g_S);
    cudaGetSymbolAddress((void**)&Y, g_Y);

    dim3 blk(256);

    // 1) Q = x @ W_theta + b_theta ; K = x @ W_phi + b_phi
    gemm_nn_kernel<<<dim3(CT / BN, NT / BM), blk>>>(x, W_theta, b_theta, Q, NT, CT, CT);
    gemm_nn_kernel<<<dim3(CT / BN, NT / BM), blk>>>(x, W_phi,   b_phi,   K, NT, CT, CT);

    // 2) S = Q @ K^T
    gemm_nt_kernel<<<dim3(NT / BN, NT / BM), blk>>>(Q, K, S, NT, NT, CT);

    // 3) row softmax in place
    softmax_kernel<<<NT, blk>>>(S);

    // 4) Y = adj @ x   (bias folds out: softmax rows sum to 1, b_k added later)
    gemm_nn_kernel<<<dim3(CT / BN, NT / BM), blk>>>(S, x, nullptr, Y, NT, CT, NT);

    // 5) out = mean_h relu(Y @ W_k[h] + b_k[h])
    heads_kernel<<<dim3(CT / BN, NT / BM), blk>>>(Y, W_k, b_k, out);
}

// round 5
// speedup vs baseline: 2.6351x; 2.6351x over previous
#include <cuda_runtime.h>
#include <cuda_bf16.h>

#define NT 8192
#define CT 512
#define HT 8

// ---------------------------------------------------------------------------
// Scratch (__device__ globals; allocation-free rule)
// ---------------------------------------------------------------------------
__device__ float          g_S[(size_t)NT * NT];                       // 268 MB
__device__ __nv_bfloat16  g_adj_h[(size_t)NT * NT];                   // 134 MB
__device__ __nv_bfloat16  g_adj_l[(size_t)NT * NT];                   // 134 MB
__device__ __nv_bfloat16  g_xh[NT * CT],  g_xl[NT * CT];
__device__ __nv_bfloat16  g_xTh[CT * NT], g_xTl[CT * NT];
__device__ __nv_bfloat16  g_Qh[NT * CT],  g_Ql[NT * CT];
__device__ __nv_bfloat16  g_Kh[NT * CT],  g_Kl[NT * CT];
__device__ __nv_bfloat16  g_Yh[NT * CT],  g_Yl[NT * CT];
__device__ __nv_bfloat16  g_WtTh[CT * CT], g_WtTl[CT * CT];
__device__ __nv_bfloat16  g_WpTh[CT * CT], g_WpTl[CT * CT];
__device__ __nv_bfloat16  g_WkTh[HT * CT * CT], g_WkTl[HT * CT * CT];

// ---------------------------------------------------------------------------
// Baseline-PTX helpers (sm_80-class features only; no 'a'-gated instructions)
// ---------------------------------------------------------------------------
__device__ __forceinline__ unsigned smem_u32(const void* p) {
    return (unsigned)__cvta_generic_to_shared(p);
}

__device__ __forceinline__ void cp16(unsigned dst, const void* src) {
    asm volatile("cp.async.cg.shared.global [%0], [%1], 16;" :: "r"(dst), "l"(src));
}
#define CP_COMMIT() asm volatile("cp.async.commit_group;" ::: "memory")
#define CP_WAIT0()  asm volatile("cp.async.wait_group 0;" ::: "memory")
#define CP_WAIT1()  asm volatile("cp.async.wait_group 1;" ::: "memory")

__device__ __forceinline__ void ldsm4(unsigned& r0, unsigned& r1,
                                      unsigned& r2, unsigned& r3, unsigned a) {
    asm volatile("ldmatrix.sync.aligned.m8n8.x4.shared.b16 {%0,%1,%2,%3}, [%4];"
                 : "=r"(r0), "=r"(r1), "=r"(r2), "=r"(r3) : "r"(a));
}

__device__ __forceinline__ void mma16816(float* c,
                                         unsigned a0, unsigned a1,
                                         unsigned a2, unsigned a3,
                                         unsigned b0, unsigned b1) {
    asm volatile("mma.sync.aligned.m16n8k16.row.col.f32.bf16.bf16.f32 "
                 "{%0,%1,%2,%3}, {%4,%5,%6,%7}, {%8,%9}, {%0,%1,%2,%3};"
                 : "+f"(c[0]), "+f"(c[1]), "+f"(c[2]), "+f"(c[3])
                 : "r"(a0), "r"(a1), "r"(a2), "r"(a3), "r"(b0), "r"(b1));
}

// ---------------------------------------------------------------------------
// Tile geometry: block tile 128x128, K-chunk 32 (bf16). 8 warps = 4(M) x 2(N),
// warp tile 32x64. SMEM rows padded to 80B (ldmatrix conflict-free).
// ---------------------------------------------------------------------------
#define TSTRIDE 80
#define TILE_B  (128 * TSTRIDE)   // 10240
#define STAGE_B (4 * TILE_B)      // 40960: Ah, Al, Bh, Bl
#define GSMEM   (2 * STAGE_B)     // 81920, double-buffered

// Load one 128-row x 32-col bf16 tile (64B/row) into padded SMEM via cp.async.
__device__ __forceinline__ void load_tile(unsigned dstbase,
                                          const __nv_bfloat16* g, int ld,
                                          int rowbase, int ktel, int tid) {
    #pragma unroll
    for (int i = 0; i < 2; ++i) {
        int idx = tid + i * 256;
        int row = idx >> 2, ch = idx & 3;
        cp16(dstbase + (unsigned)(row * TSTRIDE + ch * 16),
             (const char*)(g + (size_t)(rowbase + row) * ld + ktel) + ch * 16);
    }
}

// 3-product split compute on one K-chunk (32) from SMEM stage `st`.
// acc[fm*8+fn][4]: fm in {0,1} (m16 frags), fn in {0..7} (n8 frags).
__device__ __forceinline__ void compute_chunk(unsigned st, int wm, int wn,
                                              int lane, float acc[16][4]) {
    const unsigned sAh = st, sAl = st + TILE_B;
    const unsigned sBh = st + 2 * TILE_B, sBl = st + 3 * TILE_B;
    const int r16 = lane & 15, c16 = lane >> 4;
    const int nr = (lane & 7) + ((lane >> 4) << 3);
    const int kc = (lane >> 3) & 1;

    #pragma unroll
    for (int s = 0; s < 2; ++s) {               // two k16 steps per chunk
        unsigned ah[2][4], al[2][4];
        #pragma unroll
        for (int fm = 0; fm < 2; ++fm) {
            unsigned ao = (unsigned)((wm * 32 + fm * 16 + r16) * TSTRIDE
                                     + s * 32 + c16 * 16);
            ldsm4(ah[fm][0], ah[fm][1], ah[fm][2], ah[fm][3], sAh + ao);
            ldsm4(al[fm][0], al[fm][1], al[fm][2], al[fm][3], sAl + ao);
        }
        #pragma unroll
        for (int j = 0; j < 4; ++j) {           // pairs of n8 frags
            unsigned bo = (unsigned)((wn * 64 + j * 16 + nr) * TSTRIDE
                                     + s * 32 + kc * 16);
            unsigned bh0, bh1, bh2, bh3, bl0, bl1, bl2, bl3;
            ldsm4(bh0, bh1, bh2, bh3, sBh + bo);
            ldsm4(bl0, bl1, bl2, bl3, sBl + bo);
            #pragma unroll
            for (int fm = 0; fm < 2; ++fm) {
                float* c0 = acc[fm * 8 + 2 * j];
                float* c1 = acc[fm * 8 + 2 * j + 1];
                mma16816(c0, ah[fm][0], ah[fm][1], ah[fm][2], ah[fm][3], bh0, bh1);
                mma16816(c1, ah[fm][0], ah[fm][1], ah[fm][2], ah[fm][3], bh2, bh3);
                mma16816(c0, ah[fm][0], ah[fm][1], ah[fm][2], ah[fm][3], bl0, bl1);
                mma16816(c1, ah[fm][0], ah[fm][1], ah[fm][2], ah[fm][3], bl2, bl3);
                mma16816(c0, al[fm][0], al[fm][1], al[fm][2], al[fm][3], bh0, bh1);
                mma16816(c1, al[fm][0], al[fm][1], al[fm][2], al[fm][3], bh2, bh3);
            }
        }
    }
}

// ---------------------------------------------------------------------------
// gemm3x: C[M,N] = (Ah+Al)[M,K] @ (Bh+Bl)[N,K]^T
// mode 0: fp32 out. mode 1: bf16 hi/lo split out (+ optional fp32 bias[col]).
// grid = (N/128, M/128), 256 threads.
// ---------------------------------------------------------------------------
__global__ __launch_bounds__(256, 2)
void gemm3x_kernel(const __nv_bfloat16* __restrict__ Ah,
                   const __nv_bfloat16* __restrict__ Al, int lda,
                   const __nv_bfloat16* __restrict__ Bh,
                   const __nv_bfloat16* __restrict__ Bl, int ldb,
                   int K, const float* __restrict__ bias,
                   float* __restrict__ Cf,
                   __nv_bfloat16* __restrict__ Ch,
                   __nv_bfloat16* __restrict__ Cl, int ldc, int mode)
{
    extern __shared__ char smem[];
    const unsigned sb = smem_u32(smem);
    const int tid = threadIdx.x, lane = tid & 31, w = tid >> 5;
    const int wm = w & 3, wn = w >> 2;
    const int row0 = blockIdx.y * 128, col0 = blockIdx.x * 128;
    const int nk = K / 32;

    float acc[16][4];
    #pragma unroll
    for (int i = 0; i < 16; ++i)
        #pragma unroll
        for (int q = 0; q < 4; ++q) acc[i][q] = 0.0f;

    #pragma unroll
    for (int c = 0; c < 2; ++c) {
        unsigned st = sb + (unsigned)(c & 1) * STAGE_B;
        load_tile(st,              Ah, lda, row0, c * 32, tid);
        load_tile(st + TILE_B,     Al, lda, row0, c * 32, tid);
        load_tile(st + 2 * TILE_B, Bh, ldb, col0, c * 32, tid);
        load_tile(st + 3 * TILE_B, Bl, ldb, col0, c * 32, tid);
        CP_COMMIT();
    }

    for (int k = 0; k < nk; ++k) {
        if (k == nk - 1) { CP_WAIT0(); } else { CP_WAIT1(); }
        __syncthreads();
        compute_chunk(sb + (unsigned)(k & 1) * STAGE_B, wm, wn, lane, acc);
        __syncthreads();
        if (k + 2 < nk) {
            unsigned st = sb + (unsigned)(k & 1) * STAGE_B;
            load_tile(st,              Ah, lda, row0, (k + 2) * 32, tid);
            load_tile(st + TILE_B,     Al, lda, row0, (k + 2) * 32, tid);
            load_tile(st + 2 * TILE_B, Bh, ldb, col0, (k + 2) * 32, tid);
            load_tile(st + 3 * TILE_B, Bl, ldb, col0, (k + 2) * 32, tid);
            CP_COMMIT();
        }
    }

    const int g = lane >> 2, q = lane & 3;
    #pragma unroll
    for (int fm = 0; fm < 2; ++fm) {
        #pragma unroll
        for (int fn = 0; fn < 8; ++fn) {
            const float* a = acc[fm * 8 + fn];
            int mr  = row0 + wm * 32 + fm * 16 + g;
            int col = col0 + wn * 64 + fn * 8 + q * 2;
            if (mode == 0) {
                *reinterpret_cast<float2*>(Cf + (size_t)mr * ldc + col) =
                    make_float2(a[0], a[1]);
                *reinterpret_cast<float2*>(Cf + (size_t)(mr + 8) * ldc + col) =
                    make_float2(a[2], a[3]);
            } else {
                float b0 = bias ? bias[col] : 0.0f;
                float b1 = bias ? bias[col + 1] : 0.0f;
                #pragma unroll
                for (int half = 0; half < 2; ++half) {
                    float v0 = a[half * 2 + 0] + b0;
                    float v1 = a[half * 2 + 1] + b1;
                    __nv_bfloat16 h0 = __float2bfloat16(v0);
                    __nv_bfloat16 h1 = __float2bfloat16(v1);
                    __nv_bfloat16 l0 = __float2bfloat16(v0 - __bfloat162float(h0));
                    __nv_bfloat16 l1 = __float2bfloat16(v1 - __bfloat162float(h1));
                    size_t idx = (size_t)(mr + half * 8) * ldc + col;
                    *reinterpret_cast<__nv_bfloat162*>(Ch + idx) = __nv_bfloat162(h0, h1);
                    *reinterpret_cast<__nv_bfloat162*>(Cl + idx) = __nv_bfloat162(l0, l1);
                }
            }
        }
    }
}

// ---------------------------------------------------------------------------
// heads3x: out[m,c] = (1/H) sum_h relu( (Y @ WkT[h]^T)[m,c] + bk[h,c] )
// grid = (CT/128, NT/128), 256 threads.
// ---------------------------------------------------------------------------
__global__ __launch_bounds__(256, 1)
void heads3x_kernel(const __nv_bfloat16* __restrict__ Yh,
                    const __nv_bfloat16* __restrict__ Yl,
                    const __nv_bfloat16* __restrict__ WTh,
                    const __nv_bfloat16* __restrict__ WTl,
                    const float* __restrict__ bk,
                    float* __restrict__ out)
{
    extern __shared__ char smem[];
    const unsigned sb = smem_u32(smem);
    const int tid = threadIdx.x, lane = tid & 31, w = tid >> 5;
    const int wm = w & 3, wn = w >> 2;
    const int row0 = blockIdx.y * 128, col0 = blockIdx.x * 128;
    const int ncc = HT * 16;

    float acc[16][4], oacc[16][4];
    #pragma unroll
    for (int i = 0; i < 16; ++i)
        #pragma unroll
        for (int q = 0; q < 4; ++q) { acc[i][q] = 0.0f; oacc[i][q] = 0.0f; }

    const int g = lane >> 2, q = lane & 3;

    #pragma unroll
    for (int c = 0; c < 2; ++c) {
        int h = c >> 4, kc = c & 15;
        unsigned st = sb + (unsigned)(c & 1) * STAGE_B;
        const __nv_bfloat16* Bh = WTh + (size_t)h * CT * CT;
        const __nv_bfloat16* Bl = WTl + (size_t)h * CT * CT;
        load_tile(st,              Yh, CT, row0, kc * 32, tid);
        load_tile(st + TILE_B,     Yl, CT, row0, kc * 32, tid);
        load_tile(st + 2 * TILE_B, Bh, CT, col0, kc * 32, tid);
        load_tile(st + 3 * TILE_B, Bl, CT, col0, kc * 32, tid);
        CP_COMMIT();
    }

    for (int cc = 0; cc < ncc; ++cc) {
        const int kc = cc & 15, h = cc >> 4;
        if (cc == ncc - 1) { CP_WAIT0(); } else { CP_WAIT1(); }
        __syncthreads();
        compute_chunk(sb + (unsigned)(cc & 1) * STAGE_B, wm, wn, lane, acc);
        __syncthreads();
        if (cc + 2 < ncc) {
            int c2 = cc + 2, h2 = c2 >> 4, kc2 = c2 & 15;
            unsigned st = sb + (unsigned)(cc & 1) * STAGE_B;
            const __nv_bfloat16* Bh2 = WTh + (size_t)h2 * CT * CT;
            const __nv_bfloat16* Bl2 = WTl + (size_t)h2 * CT * CT;
            load_tile(st,              Yh, CT, row0, kc2 * 32, tid);
            load_tile(st + TILE_B,     Yl, CT, row0, kc2 * 32, tid);
            load_tile(st + 2 * TILE_B, Bh2, CT, col0, kc2 * 32, tid);
            load_tile(st + 3 * TILE_B, Bl2, CT, col0, kc2 * 32, tid);
            CP_COMMIT();
        }
        if (kc == 15) {     // head complete: bias + relu accumulate, reset acc
            #pragma unroll
            for (int fm = 0; fm < 2; ++fm)
                #pragma unroll
                for (int fn = 0; fn < 8; ++fn) {
                    int col = col0 + wn * 64 + fn * 8 + q * 2;
                    float b0 = bk[(size_t)h * CT + col];
                    float b1 = bk[(size_t)h * CT + col + 1];
                    float* a = acc[fm * 8 + fn];
                    float* o = oacc[fm * 8 + fn];
                    o[0] += fmaxf(a[0] + b0, 0.0f);
                    o[1] += fmaxf(a[1] + b1, 0.0f);
                    o[2] += fmaxf(a[2] + b0, 0.0f);
                    o[3] += fmaxf(a[3] + b1, 0.0f);
                    a[0] = a[1] = a[2] = a[3] = 0.0f;
                }
        }
    }

    #pragma unroll
    for (int fm = 0; fm < 2; ++fm)
        #pragma unroll
        for (int fn = 0; fn < 8; ++fn) {
            const float* o = oacc[fm * 8 + fn];
            int mr  = row0 + wm * 32 + fm * 16 + g;
            int col = col0 + wn * 64 + fn * 8 + q * 2;
            *reinterpret_cast<float2*>(out + (size_t)mr * CT + col) =
                make_float2(o[0] * 0.125f, o[1] * 0.125f);
            *reinterpret_cast<float2*>(out + (size_t)(mr + 8) * CT + col) =
                make_float2(o[2] * 0.125f, o[3] * 0.125f);
        }
}

// ---------------------------------------------------------------------------
// fp32 -> bf16 hi/lo elementwise split
// ---------------------------------------------------------------------------
__global__ void split_kernel(const float* __restrict__ in,
                             __nv_bfloat16* __restrict__ oh,
                             __nv_bfloat16* __restrict__ ol, int n)
{
    int i = blockIdx.x * blockDim.x + threadIdx.x;
    if (i < n) {
        float v = in[i];
        __nv_bfloat16 h = __float2bfloat16(v);
        oh[i] = h;
        ol[i] = __float2bfloat16(v - __bfloat162float(h));
    }
}

// ---------------------------------------------------------------------------
// batched transpose + split: in[z][R][C] -> out_h/out_l[z][C][R]
// ---------------------------------------------------------------------------
__global__ void transpose_split_kernel(const float* __restrict__ in,
                                       __nv_bfloat16* __restrict__ oh,
                                       __nv_bfloat16* __restrict__ ol,
                                       int R, int C)
{
    __shared__ float t[32][33];
    size_t zoff = (size_t)blockIdx.z * R * C;
    const float* pin = in + zoff;
    __nv_bfloat16* ph = oh + zoff;
    __nv_bfloat16* pl = ol + zoff;
    int x0 = blockIdx.x * 32, y0 = blockIdx.y * 32;
    int tx = threadIdx.x, ty = threadIdx.y;
    #pragma unroll
    for (int i = 0; i < 32; i += 8)
        t[ty + i][tx] = pin[(size_t)(y0 + ty + i) * C + x0 + tx];
    __syncthreads();
    #pragma unroll
    for (int i = 0; i < 32; i += 8) {
        float v = t[tx][ty + i];
        __nv_bfloat16 h = __float2bfloat16(v);
        size_t idx = (size_t)(x0 + ty + i) * R + y0 + tx;
        ph[idx] = h;
        pl[idx] = __float2bfloat16(v - __bfloat162float(h));
    }
}

// ---------------------------------------------------------------------------
// row softmax of S (fp32) -> adj hi/lo bf16
// ---------------------------------------------------------------------------
__global__ __launch_bounds__(256)
void softmax_split_kernel(const float* __restrict__ S,
                          __nv_bfloat16* __restrict__ adjh,
                          __nv_bfloat16* __restrict__ adjl)
{
    __shared__ float row[NT];
    __shared__ float red[256];
    const int tid = threadIdx.x;
    const float* p = S + (size_t)blockIdx.x * NT;
    const float4* p4 = reinterpret_cast<const float4*>(p);
    float4* r4 = reinterpret_cast<float4*>(row);

    float mx = -3.0e38f;
    for (int i = tid; i < NT / 4; i += 256) {
        float4 v = p4[i];
        r4[i] = v;
        mx = fmaxf(mx, fmaxf(fmaxf(v.x, v.y), fmaxf(v.z, v.w)));
    }
    red[tid] = mx; __syncthreads();
    for (int s = 128; s > 0; s >>= 1) {
        if (tid < s) red[tid] = fmaxf(red[tid], red[tid + s]);
        __syncthreads();
    }
    mx = red[0]; __syncthreads();

    float sum = 0.0f;
    for (int i = tid; i < NT / 4; i += 256) {
        float4 v = r4[i];
        v.x = expf(v.x - mx); v.y = expf(v.y - mx);
        v.z = expf(v.z - mx); v.w = expf(v.w - mx);
        sum += (v.x + v.y) + (v.z + v.w);
        r4[i] = v;
    }
    red[tid] = sum; __syncthreads();
    for (int s = 128; s > 0; s >>= 1) {
        if (tid < s) red[tid] += red[tid + s];
        __syncthreads();
    }
    float inv = 1.0f / red[0];
    __syncthreads();

    size_t ro = (size_t)blockIdx.x * NT;
    for (int i = tid * 2; i < NT; i += 512) {
        float v0 = row[i] * inv, v1 = row[i + 1] * inv;
        __nv_bfloat16 h0 = __float2bfloat16(v0);
        __nv_bfloat16 h1 = __float2bfloat16(v1);
        __nv_bfloat16 l0 = __float2bfloat16(v0 - __bfloat162float(h0));
        __nv_bfloat16 l1 = __float2bfloat16(v1 - __bfloat162float(h1));
        *reinterpret_cast<__nv_bfloat162*>(adjh + ro + i) = __nv_bfloat162(h0, h1);
        *reinterpret_cast<__nv_bfloat162*>(adjl + ro + i) = __nv_bfloat162(l0, l1);
    }
}

// ---------------------------------------------------------------------------
extern "C" void kernel_launch(void* const* d_in, const int* in_sizes, int n_in,
                              void* d_out, int out_size)
{
    const float* x       = (const float*)d_in[0];
    const float* W_theta = (const float*)d_in[1];
    const float* b_theta = (const float*)d_in[2];
    const float* W_phi   = (const float*)d_in[3];
    const float* b_phi   = (const float*)d_in[4];
    const float* W_k     = (const float*)d_in[5];
    const float* b_k     = (const float*)d_in[6];
    float* out = (float*)d_out;

    static int attr_done = 0;
    if (!attr_done) {
        cudaFuncSetAttribute(gemm3x_kernel,
            cudaFuncAttributeMaxDynamicSharedMemorySize, GSMEM);
        cudaFuncSetAttribute(heads3x_kernel,
            cudaFuncAttributeMaxDynamicSharedMemorySize, GSMEM);
        attr_done = 1;
    }

    float* S;
    __nv_bfloat16 *adjh, *adjl, *xh, *xl, *xTh, *xTl;
    __nv_bfloat16 *Qh, *Ql, *Kh, *Kl, *Yh, *Yl;
    __nv_bfloat16 *WtTh, *WtTl, *WpTh, *WpTl, *WkTh, *WkTl;
    cudaGetSymbolAddress((void**)&S, g_S);
    cudaGetSymbolAddress((void**)&adjh, g_adj_h);
    cudaGetSymbolAddress((void**)&adjl, g_adj_l);
    cudaGetSymbolAddress((void**)&xh, g_xh);   cudaGetSymbolAddress((void**)&xl, g_xl);
    cudaGetSymbolAddress((void**)&xTh, g_xTh); cudaGetSymbolAddress((void**)&xTl, g_xTl);
    cudaGetSymbolAddress((void**)&Qh, g_Qh);   cudaGetSymbolAddress((void**)&Ql, g_Ql);
    cudaGetSymbolAddress((void**)&Kh, g_Kh);   cudaGetSymbolAddress((void**)&Kl, g_Kl);
    cudaGetSymbolAddress((void**)&Yh, g_Yh);   cudaGetSymbolAddress((void**)&Yl, g_Yl);
    cudaGetSymbolAddress((void**)&WtTh, g_WtTh); cudaGetSymbolAddress((void**)&WtTl, g_WtTl);
    cudaGetSymbolAddress((void**)&WpTh, g_WpTh); cudaGetSymbolAddress((void**)&WpTl, g_WpTl);
    cudaGetSymbolAddress((void**)&WkTh, g_WkTh); cudaGetSymbolAddress((void**)&WkTl, g_WkTl);

    dim3 t32x8(32, 8);

    // operand prep
    split_kernel<<<(NT * CT + 255) / 256, 256>>>(x, xh, xl, NT * CT);
    transpose_split_kernel<<<dim3(CT / 32, NT / 32, 1), t32x8>>>(x, xTh, xTl, NT, CT);
    transpose_split_kernel<<<dim3(CT / 32, CT / 32, 1), t32x8>>>(W_theta, WtTh, WtTl, CT, CT);
    transpose_split_kernel<<<dim3(CT / 32, CT / 32, 1), t32x8>>>(W_phi, WpTh, WpTl, CT, CT);
    transpose_split_kernel<<<dim3(CT / 32, CT / 32, HT), t32x8>>>(W_k, WkTh, WkTl, CT, CT);

    // projections: Q = x@Wt + bt, K = x@Wp + bp  (split outputs)
    gemm3x_kernel<<<dim3(CT / 128, NT / 128), 256, GSMEM>>>(
        xh, xl, CT, WtTh, WtTl, CT, CT, b_theta,
        nullptr, Qh, Ql, CT, 1);
    gemm3x_kernel<<<dim3(CT / 128, NT / 128), 256, GSMEM>>>(
        xh, xl, CT, WpTh, WpTl, CT, CT, b_phi,
        nullptr, Kh, Kl, CT, 1);

    // S = Q @ K^T (fp32 out)
    gemm3x_kernel<<<dim3(NT / 128, NT / 128), 256, GSMEM>>>(
        Qh, Ql, CT, Kh, Kl, CT, CT, nullptr,
        S, nullptr, nullptr, NT, 0);

    // adj = softmax(S) -> bf16 hi/lo
    softmax_split_kernel<<<NT, 256>>>(S, adjh, adjl);

    // Y = adj @ x (split outputs)
    gemm3x_kernel<<<dim3(CT / 128, NT / 128), 256, GSMEM>>>(
        adjh, adjl, NT, xTh, xTl, NT, NT, nullptr,
        nullptr, Yh, Yl, CT, 1);

    // out = mean_h relu(Y @ Wk[h] + bk[h])
    heads3x_kernel<<<dim3(CT / 128, NT / 128), 256, GSMEM>>>(
        Yh, Yl, WkTh, WkTl, b_k, out);
}